// round 7
// baseline (speedup 1.0000x reference)
#include <cuda_runtime.h>
#include <cuda_bf16.h>
#include <cstdint>

// SparseBoundaryContent: x [16, 512, 64] f32.
// boundary(i,j) = (x[i]+x[j])/2 on masked cells, content(i,j) = max(x[i..j])
// on masked cells, 0 elsewhere.
// Output layout (flat f32): [boundary B*D*N*N][content B*D*N*N][mask B*N*N].
//
// R6: 8 rows per CTA through ONE smem tile pair. Unmasked cells are zeroed
// once and never touched again; each row only rewrites the 1104 masked cells
// and bulk-stores 2x16KB via the async proxy. Warp 0 rebuilds the sparse-max
// table (syncwarp-only) while the previous row's bulk store drains.

#define NB 16
#define ND 512
#define NN 64
#define NCELLS 4096          // 64*64 cells per (b,d) row
#define NMASKED 1104         // masked cells per tile (incl. diagonal)
#define RPC 8                // rows per CTA

constexpr bool cell_mask_ct(int i, int j) {
    int d = j - i;
    if (d < 0)  return false;
    if (d <= 15) return true;                              // stride-1 offsets 0..15
    if (d <= 31) return (d & 1) && !(i & 1);               // stride-2: odd 17..31, i even
    return (d >= 35) && ((d & 3) == 3) && !(i & 3);        // stride-4: 35,39,..,63, i%4==0
}

struct MaskTab { float m[NCELLS]; };
constexpr MaskTab gen_mask() {
    MaskTab t{};
    for (int i = 0; i < NN; i++)
        for (int j = 0; j < NN; j++)
            t.m[i * NN + j] = cell_mask_ct(i, j) ? 1.0f : 0.0f;
    return t;
}
__device__ constexpr MaskTab g_mask = gen_mask();

struct Meta { unsigned int m[NMASKED]; };
constexpr Meta gen_meta() {
    Meta t{};
    int cnt = 0;
    for (int i = 0; i < NN; i++) {
        for (int j = 0; j < NN; j++) {
            if (!cell_mask_ct(i, j)) continue;
            int len = j - i + 1;
            int k = 0;
            while ((1 << (k + 1)) <= len) k++;             // floor(log2(len))
            int ri = j + 1 - (1 << k);
            unsigned offL = (unsigned)(k * NN + i);
            unsigned offR = (unsigned)(k * NN + ri);
            t.m[cnt++] = (unsigned)(i * NN + j) | (offL << 12) | (offR << 21);
        }
    }
    return t;
}
__device__ constexpr Meta g_meta = gen_meta();

__device__ __forceinline__ uint32_t smem_u32(const void* p) {
    uint32_t a;
    asm("{ .reg .u64 t; cvta.to.shared.u64 t, %1; cvt.u32.u64 %0, t; }"
        : "=r"(a) : "l"(p));
    return a;
}

__global__ void __launch_bounds__(256)
sbc_kernel(const float* __restrict__ x,
           float* __restrict__ boundary,
           float* __restrict__ content,
           float* __restrict__ mask_out)
{
    __shared__ float Mf[7 * NN];                 // sparse max table; Mf[0..63] = x row
    __shared__ alignas(128) float bt[NCELLS];    // boundary tile (16 KB)
    __shared__ alignas(128) float ct[NCELLS];    // content tile  (16 KB)

    const int bd0 = blockIdx.x * RPC;
    const int tid = threadIdx.x;
    const int wid = tid >> 5;
    const int lid = tid & 31;

    // Zero-fill both tiles ONCE; unmasked cells stay zero for all RPC rows.
    const float4 z = make_float4(0.f, 0.f, 0.f, 0.f);
    #pragma unroll
    for (int p = 0; p < 4; p++) {
        reinterpret_cast<float4*>(bt)[p * 256 + tid] = z;
        reinterpret_cast<float4*>(ct)[p * 256 + tid] = z;
    }

    // CTAs holding a d==0 row emit the broadcast mask slice for their batch.
    if ((bd0 & (ND - 1)) == 0) {
        float* mp = mask_out + (size_t)(bd0 >> 9) * NCELLS;
        #pragma unroll
        for (int p = 0; p < 4; p++) {
            const int c0 = (p * 256 + tid) * 4;
            *reinterpret_cast<float4*>(mp + c0) =
                *reinterpret_cast<const float4*>(&g_mask.m[c0]);
        }
    }

    for (int r = 0; r < RPC; r++) {
        const int bd = bd0 + r;

        // Warp 0 rebuilds the sparse-max table (overlaps prev store drain).
        if (wid == 0) {
            const float* xr = x + (size_t)bd * NN;
            Mf[lid]      = xr[lid];
            Mf[lid + 32] = xr[lid + 32];
            __syncwarp();
            #pragma unroll
            for (int k = 1; k < 7; k++) {
                const int h  = 1 << (k - 1);
                const int e1 = lid + 32;
                int o0 = lid + h; if (o0 > 63) o0 = 63;
                int o1 = e1  + h; if (o1 > 63) o1 = 63;
                const float a = fmaxf(Mf[(k - 1) * NN + lid], Mf[(k - 1) * NN + o0]);
                const float b = fmaxf(Mf[(k - 1) * NN + e1],  Mf[(k - 1) * NN + o1]);
                Mf[k * NN + lid] = a;
                Mf[k * NN + e1]  = b;
                __syncwarp();
            }
        }
        __syncthreads();                         // Mf ready for all warps

        // Previous row's bulk store must finish before rewriting the tiles.
        if (tid == 0)
            asm volatile("cp.async.bulk.wait_group 0;" ::: "memory");
        __syncthreads();

        // Scatter boundary + content at the 1104 masked cells.
        #pragma unroll
        for (int p = 0; p < 5; p++) {
            int idx = p * 256 + tid;
            if (idx < NMASKED) {
                const unsigned m    = g_meta.m[idx];
                const int      cell = m & 4095u;
                const int      i    = cell >> 6;
                const int      j    = cell & 63;
                bt[cell] = (Mf[i] + Mf[j]) * 0.5f;
                ct[cell] = fmaxf(Mf[(m >> 12) & 511u], Mf[(m >> 21) & 511u]);
            }
        }

        asm volatile("fence.proxy.async.shared::cta;" ::: "memory");
        __syncthreads();

        if (tid == 0) {
            const uint32_t sb = smem_u32(bt);
            const uint32_t sc = smem_u32(ct);
            float* gb = boundary + (size_t)bd * NCELLS;
            float* gc = content  + (size_t)bd * NCELLS;
            asm volatile("cp.async.bulk.global.shared::cta.bulk_group [%0], [%1], %2;"
                         :: "l"(gb), "r"(sb), "n"(NCELLS * 4) : "memory");
            asm volatile("cp.async.bulk.global.shared::cta.bulk_group [%0], [%1], %2;"
                         :: "l"(gc), "r"(sc), "n"(NCELLS * 4) : "memory");
            asm volatile("cp.async.bulk.commit_group;" ::: "memory");
        }
        // No barrier needed here: next iteration only touches Mf (not read by
        // TMA), and the wait_group above protects the tiles.
    }

    // Drain the final store before CTA teardown.
    if (tid == 0)
        asm volatile("cp.async.bulk.wait_group 0;" ::: "memory");
}

extern "C" void kernel_launch(void* const* d_in, const int* in_sizes, int n_in,
                              void* d_out, int out_size) {
    const float* x = (const float*)d_in[0];
    float* out = (float*)d_out;

    const size_t map_elems = (size_t)NB * ND * NN * NN;   // 33,554,432
    float* boundary = out;
    float* content  = out + map_elems;
    float* mask_out = out + 2 * map_elems;

    sbc_kernel<<<(NB * ND) / RPC, 256>>>(x, boundary, content, mask_out);
}

// round 9
// speedup vs baseline: 1.1152x; 1.1152x over previous
#include <cuda_runtime.h>
#include <cuda_bf16.h>
#include <cstdint>

// SparseBoundaryContent: x [16, 512, 64] f32.
// boundary(i,j) = (x[i]+x[j])/2 on masked cells, content(i,j) = max(x[i..j])
// on masked cells, 0 elsewhere.
// Output layout (flat f32): [boundary B*D*N*N][content B*D*N*N][mask B*N*N].
//
// R8: same as R7 (8 rows/CTA, double-buffered smem tile pairs, cp.async.bulk
// stores, zero-fill once) but with the non-deterministic static guard removed:
// cudaFuncSetAttribute is called unconditionally on every kernel_launch.

#define NB 16
#define ND 512
#define NN 64
#define NCELLS 4096          // 64*64 cells per (b,d) row
#define NMASKED 1104         // masked cells per tile (incl. diagonal)
#define RPC 8                // rows per CTA

// dynamic smem layout (floats): Mf[448] | bt0[4096] ct0[4096] bt1[4096] ct1[4096]
#define MF_OFF   0
#define TILE_OFF 448
#define SMEM_FLOATS (448 + 4 * 4096)
#define SMEM_BYTES  (SMEM_FLOATS * 4)

constexpr bool cell_mask_ct(int i, int j) {
    int d = j - i;
    if (d < 0)  return false;
    if (d <= 15) return true;                              // stride-1 offsets 0..15
    if (d <= 31) return (d & 1) && !(i & 1);               // stride-2: odd 17..31, i even
    return (d >= 35) && ((d & 3) == 3) && !(i & 3);        // stride-4: 35,39,..,63, i%4==0
}

struct MaskTab { float m[NCELLS]; };
constexpr MaskTab gen_mask() {
    MaskTab t{};
    for (int i = 0; i < NN; i++)
        for (int j = 0; j < NN; j++)
            t.m[i * NN + j] = cell_mask_ct(i, j) ? 1.0f : 0.0f;
    return t;
}
__device__ constexpr MaskTab g_mask = gen_mask();

struct Meta { unsigned int m[NMASKED]; };
constexpr Meta gen_meta() {
    Meta t{};
    int cnt = 0;
    for (int i = 0; i < NN; i++) {
        for (int j = 0; j < NN; j++) {
            if (!cell_mask_ct(i, j)) continue;
            int len = j - i + 1;
            int k = 0;
            while ((1 << (k + 1)) <= len) k++;             // floor(log2(len))
            int ri = j + 1 - (1 << k);
            unsigned offL = (unsigned)(k * NN + i);
            unsigned offR = (unsigned)(k * NN + ri);
            t.m[cnt++] = (unsigned)(i * NN + j) | (offL << 12) | (offR << 21);
        }
    }
    return t;
}
__device__ constexpr Meta g_meta = gen_meta();

__device__ __forceinline__ uint32_t smem_u32(const void* p) {
    uint32_t a;
    asm("{ .reg .u64 t; cvta.to.shared.u64 t, %1; cvt.u32.u64 %0, t; }"
        : "=r"(a) : "l"(p));
    return a;
}

__global__ void __launch_bounds__(256)
sbc_kernel(const float* __restrict__ x,
           float* __restrict__ boundary,
           float* __restrict__ content,
           float* __restrict__ mask_out)
{
    extern __shared__ float smem[];
    float* Mf   = smem + MF_OFF;                 // sparse max table (7*64)
    float* tile = smem + TILE_OFF;               // 4 x 4096 floats

    const int bd0 = blockIdx.x * RPC;
    const int tid = threadIdx.x;
    const int wid = tid >> 5;
    const int lid = tid & 31;

    // Zero-fill all 4 tiles ONCE; unmasked cells stay zero for all rows.
    const float4 z = make_float4(0.f, 0.f, 0.f, 0.f);
    #pragma unroll
    for (int p = 0; p < 16; p++)
        reinterpret_cast<float4*>(tile)[p * 256 + tid] = z;

    // Preload the 5 meta descriptors this thread owns (reused all rows).
    unsigned mreg[5];
    #pragma unroll
    for (int p = 0; p < 5; p++) {
        int idx = p * 256 + tid;
        mreg[p] = (idx < NMASKED) ? g_meta.m[idx] : 0xFFFFFFFFu;
    }

    // CTAs holding a d==0 row emit the broadcast mask slice for their batch.
    if ((bd0 & (ND - 1)) == 0) {
        float* mp = mask_out + (size_t)(bd0 >> 9) * NCELLS;
        #pragma unroll
        for (int p = 0; p < 4; p++) {
            const int c0 = (p * 256 + tid) * 4;
            *reinterpret_cast<float4*>(mp + c0) =
                *reinterpret_cast<const float4*>(&g_mask.m[c0]);
        }
    }

    for (int r = 0; r < RPC; r++) {
        const int bd = bd0 + r;
        float* bt = tile + (r & 1) * (2 * NCELLS);
        float* ct = bt + NCELLS;

        // Warp 0: rebuild sparse-max table. Thread 224 (warp 7): ensure the
        // store that last used THIS buffer (row r-2) has drained. Concurrent.
        if (wid == 0) {
            const float* xr = x + (size_t)bd * NN;
            Mf[lid]      = xr[lid];
            Mf[lid + 32] = xr[lid + 32];
            __syncwarp();
            #pragma unroll
            for (int k = 1; k < 7; k++) {
                const int h  = 1 << (k - 1);
                const int e1 = lid + 32;
                int o0 = lid + h; if (o0 > 63) o0 = 63;
                int o1 = e1  + h; if (o1 > 63) o1 = 63;
                const float a = fmaxf(Mf[(k - 1) * NN + lid], Mf[(k - 1) * NN + o0]);
                const float b = fmaxf(Mf[(k - 1) * NN + e1],  Mf[(k - 1) * NN + o1]);
                Mf[k * NN + lid] = a;
                Mf[k * NN + e1]  = b;
                __syncwarp();
            }
        } else if (tid == 224) {
            asm volatile("cp.async.bulk.wait_group 1;" ::: "memory");
        }
        __syncthreads();      // Mf ready AND buffer free

        // Scatter boundary + content at the 1104 masked cells.
        #pragma unroll
        for (int p = 0; p < 5; p++) {
            const unsigned m = mreg[p];
            if (m != 0xFFFFFFFFu) {
                const int cell = m & 4095u;
                const int i    = cell >> 6;
                const int j    = cell & 63;
                bt[cell] = (Mf[i] + Mf[j]) * 0.5f;
                ct[cell] = fmaxf(Mf[(m >> 12) & 511u], Mf[(m >> 21) & 511u]);
            }
        }

        asm volatile("fence.proxy.async.shared::cta;" ::: "memory");
        __syncthreads();      // scatter (and initial zero-fill) visible to async proxy

        if (tid == 224) {
            const uint32_t sb = smem_u32(bt);
            const uint32_t sc = smem_u32(ct);
            float* gb = boundary + (size_t)bd * NCELLS;
            float* gc = content  + (size_t)bd * NCELLS;
            asm volatile("cp.async.bulk.global.shared::cta.bulk_group [%0], [%1], %2;"
                         :: "l"(gb), "r"(sb), "n"(NCELLS * 4) : "memory");
            asm volatile("cp.async.bulk.global.shared::cta.bulk_group [%0], [%1], %2;"
                         :: "l"(gc), "r"(sc), "n"(NCELLS * 4) : "memory");
            asm volatile("cp.async.bulk.commit_group;" ::: "memory");
        }
        // Next iteration: warp 0 overwrites only Mf (not read by TMA); the
        // buffer it scatters into is protected by wait_group 1 above.
    }

    // Drain all stores before CTA teardown (smem reuse safety).
    if (tid == 224)
        asm volatile("cp.async.bulk.wait_group 0;" ::: "memory");
}

extern "C" void kernel_launch(void* const* d_in, const int* in_sizes, int n_in,
                              void* d_out, int out_size) {
    const float* x = (const float*)d_in[0];
    float* out = (float*)d_out;

    const size_t map_elems = (size_t)NB * ND * NN * NN;   // 33,554,432
    float* boundary = out;
    float* content  = out + map_elems;
    float* mask_out = out + 2 * map_elems;

    // Unconditional (idempotent, deterministic, not a stream operation).
    cudaFuncSetAttribute(sbc_kernel,
                         cudaFuncAttributeMaxDynamicSharedMemorySize,
                         SMEM_BYTES);

    sbc_kernel<<<(NB * ND) / RPC, 256, SMEM_BYTES>>>(x, boundary, content, mask_out);
}